// round 2
// baseline (speedup 1.0000x reference)
#include <cuda_runtime.h>
#include <cstdint>

#define BN_SCALE 0.9999950000374997f
#define FLTMAX 3.402823466e+38f

// ------------------------- device scratch -------------------------
__device__ float g_T[32768 * 512];        // [a|c] buffer, reused across layers (64MB)
__device__ float g_h1[32768 * 64];
__device__ float g_h2[32768 * 128];
__device__ float g_h3[32768 * 256];
__device__ float g_d2[128 * 256 * 256];   // 32MB, reused
__device__ float g_sq[32768];
__device__ int   g_idx[128 * 256 * 16];
__device__ float g_W1p[6 * 128];   __device__ float g_b1p[128];
__device__ float g_W2p[64 * 256];  __device__ float g_b2p[256];
__device__ float g_W3p[128 * 512]; __device__ float g_b3p[512];

// ------------------------- weight prep ----------------------------
// Wp[k][c]      (c<C)  = alpha_c * (W[k][c] - W[Cin+k][c])      (xi coefficient)
// Wp[k][C+c]           = alpha_c * W[Cin+k][c]                  (xj coefficient)
// bp[c] = alpha_c*b[c] + be[c] (first half), 0 (second half); alpha = g*BN_SCALE
__global__ void prepw(const float* __restrict__ W, const float* __restrict__ b,
                      const float* __restrict__ g, const float* __restrict__ be,
                      float* __restrict__ Wp, float* __restrict__ bp,
                      int Cin, int C) {
    int n2 = 2 * C;
    int total = Cin * n2;
    for (int t = blockIdx.x * blockDim.x + threadIdx.x; t < total + n2;
         t += gridDim.x * blockDim.x) {
        if (t < total) {
            int k = t / n2, c = t % n2;
            float out;
            if (c < C) out = g[c] * BN_SCALE * (W[k * C + c] - W[(Cin + k) * C + c]);
            else { int cc = c - C; out = g[cc] * BN_SCALE * W[(Cin + k) * C + cc]; }
            Wp[t] = out;
        } else {
            int c = t - total;
            bp[c] = (c < C) ? (g[c] * BN_SCALE * b[c] + be[c]) : 0.0f;
        }
    }
}

// ------------------------- row sum-of-squares ---------------------
__global__ void rowsq(const float* __restrict__ X, float* __restrict__ sq, int D) {
    int row = blockIdx.x * 8 + (threadIdx.x >> 5);
    int lane = threadIdx.x & 31;
    float s = 0.0f;
    for (int k = lane; k < D; k += 32) { float v = X[(size_t)row * D + k]; s += v * v; }
    #pragma unroll
    for (int o = 16; o; o >>= 1) s += __shfl_xor_sync(0xFFFFFFFFu, s, o);
    if (lane == 0) sq[row] = s;
}

// ------------------------- batched Gram -> d2 ---------------------
// d2[b][i][j] = sq_i + sq_j - 2 * <H_i, H_j>, diag = +inf.  256x256 per batch.
// Software-pipelined: next K-tile prefetched into registers during compute.
__global__ __launch_bounds__(256) void gramd2(const float* __restrict__ H,
                                              const float* __restrict__ sq,
                                              float* __restrict__ d2, int D) {
    __shared__ __align__(16) float As[16][132];
    __shared__ __align__(16) float Bs[16][132];
    int b = blockIdx.z;
    int i0 = blockIdx.y * 128, j0 = blockIdx.x * 128;
    const float* Hb = H + (size_t)b * 256 * D;
    int tid = threadIdx.x;
    int tx = tid & 15, ty = tid >> 4;
    int lk = tid & 15, li = tid >> 4;

    float acc[8][8];
    #pragma unroll
    for (int r = 0; r < 8; r++)
        #pragma unroll
        for (int s = 0; s < 8; s++) acc[r][s] = 0.0f;

    float pa[8], pb[8];
    #pragma unroll
    for (int it = 0; it < 8; ++it) {
        int i = li + it * 16;
        pa[it] = (lk < D) ? Hb[(size_t)(i0 + i) * D + lk] : 0.0f;
        pb[it] = (lk < D) ? Hb[(size_t)(j0 + i) * D + lk] : 0.0f;
    }

    for (int k0 = 0; k0 < D; k0 += 16) {
        #pragma unroll
        for (int it = 0; it < 8; ++it) {
            As[lk][li + it * 16] = pa[it];
            Bs[lk][li + it * 16] = pb[it];
        }
        __syncthreads();
        if (k0 + 16 < D) {
            int kn = k0 + 16 + lk;
            #pragma unroll
            for (int it = 0; it < 8; ++it) {
                int i = li + it * 16;
                pa[it] = (kn < D) ? Hb[(size_t)(i0 + i) * D + kn] : 0.0f;
                pb[it] = (kn < D) ? Hb[(size_t)(j0 + i) * D + kn] : 0.0f;
            }
        }
        #pragma unroll
        for (int kk = 0; kk < 16; ++kk) {
            float a[8], bb[8];
            *(float4*)&a[0]  = *(const float4*)&As[kk][ty * 8];
            *(float4*)&a[4]  = *(const float4*)&As[kk][ty * 8 + 4];
            *(float4*)&bb[0] = *(const float4*)&Bs[kk][tx * 8];
            *(float4*)&bb[4] = *(const float4*)&Bs[kk][tx * 8 + 4];
            #pragma unroll
            for (int r = 0; r < 8; r++)
                #pragma unroll
                for (int s = 0; s < 8; s++) acc[r][s] += a[r] * bb[s];
        }
        __syncthreads();
    }

    const float* sqb = sq + b * 256;
    #pragma unroll
    for (int r = 0; r < 8; r++) {
        int row = i0 + ty * 8 + r;
        float si = sqb[row];
        #pragma unroll
        for (int s = 0; s < 8; s++) {
            int col = j0 + tx * 8 + s;
            float val = si + sqb[col] - 2.0f * acc[r][s];
            if (row == col) val = FLTMAX;
            d2[((size_t)b * 256 + row) * 256 + col] = val;
        }
    }
}

// ------------------------- top-16 smallest ------------------------
// Reads column i (== row i by bitwise symmetry) so accesses are coalesced.
__global__ void topk16(const float* __restrict__ d2, int* __restrict__ idx) {
    int b = blockIdx.x, i = threadIdx.x;
    const float* dp = d2 + (size_t)b * 65536;
    float bd[16]; int bi[16];
    #pragma unroll
    for (int t = 0; t < 16; t++) { bd[t] = FLTMAX; bi[t] = -1; }
    for (int j = 0; j < 256; j++) {
        float d = dp[j * 256 + i];
        if (d < bd[15]) {
            bd[15] = d; bi[15] = j;
            #pragma unroll
            for (int t = 15; t > 0; --t) {
                if (bd[t] < bd[t - 1]) {
                    float td = bd[t]; bd[t] = bd[t - 1]; bd[t - 1] = td;
                    int ti = bi[t];   bi[t] = bi[t - 1]; bi[t - 1] = ti;
                }
            }
        }
    }
    int* op = idx + ((size_t)b * 256 + i) * 16;
    #pragma unroll
    for (int t = 0; t < 16; t++) op[t] = bi[t];
}

// ------------------------- main SGEMM (A[MxK] @ W[KxN] + bias) ----
// 128x128 tile, 8x8 register blocking, register-prefetch pipeline.
__global__ __launch_bounds__(256) void sgemm(const float* __restrict__ A,
                                             const float* __restrict__ W,
                                             const float* __restrict__ bias,
                                             float* __restrict__ C,
                                             int M, int K, int N) {
    __shared__ __align__(16) float As[16][132];
    __shared__ __align__(16) float Bs[16][132];
    int i0 = blockIdx.y * 128;
    int j0 = blockIdx.x * 128;
    int tid = threadIdx.x;
    int tx = tid & 15, ty = tid >> 4;
    int lka = tid & 15, lia = tid >> 4;   // A-stage: thread loads col lka, rows lia+16*it
    int ljb = tid & 127, lkb = tid >> 7;  // B-stage: thread loads col ljb, rows lkb+2*it

    float acc[8][8];
    #pragma unroll
    for (int r = 0; r < 8; r++)
        #pragma unroll
        for (int s = 0; s < 8; s++) acc[r][s] = 0.0f;

    float pa[8], pb[8];
    #pragma unroll
    for (int it = 0; it < 8; ++it) {
        pa[it] = (lka < K) ? A[(size_t)(i0 + lia + it * 16) * K + lka] : 0.0f;
        int kb = lkb + it * 2;
        pb[it] = (kb < K) ? W[(size_t)kb * N + j0 + ljb] : 0.0f;
    }

    for (int k0 = 0; k0 < K; k0 += 16) {
        #pragma unroll
        for (int it = 0; it < 8; ++it) {
            As[lka][lia + it * 16] = pa[it];
            Bs[lkb + it * 2][ljb] = pb[it];
        }
        __syncthreads();
        if (k0 + 16 < K) {
            #pragma unroll
            for (int it = 0; it < 8; ++it) {
                int ka = k0 + 16 + lka;
                pa[it] = (ka < K) ? A[(size_t)(i0 + lia + it * 16) * K + ka] : 0.0f;
                int kb = k0 + 16 + lkb + it * 2;
                pb[it] = (kb < K) ? W[(size_t)kb * N + j0 + ljb] : 0.0f;
            }
        }
        #pragma unroll
        for (int kk = 0; kk < 16; ++kk) {
            float a[8], bb[8];
            *(float4*)&a[0]  = *(const float4*)&As[kk][ty * 8];
            *(float4*)&a[4]  = *(const float4*)&As[kk][ty * 8 + 4];
            *(float4*)&bb[0] = *(const float4*)&Bs[kk][tx * 8];
            *(float4*)&bb[4] = *(const float4*)&Bs[kk][tx * 8 + 4];
            #pragma unroll
            for (int r = 0; r < 8; r++)
                #pragma unroll
                for (int s = 0; s < 8; s++) acc[r][s] += a[r] * bb[s];
        }
        __syncthreads();
    }

    #pragma unroll
    for (int r = 0; r < 8; r++) {
        int row = i0 + ty * 8 + r;
        #pragma unroll
        for (int s = 0; s < 8; s += 4) {
            int col = j0 + tx * 8 + s;
            float4 v;
            v.x = acc[r][s + 0] + bias[col + 0];
            v.y = acc[r][s + 1] + bias[col + 1];
            v.z = acc[r][s + 2] + bias[col + 2];
            v.w = acc[r][s + 3] + bias[col + 3];
            *(float4*)&C[(size_t)row * N + col] = v;
        }
    }
}

// ------------------------- edge max -------------------------------
// T[row][0..C) = a' (affine-folded xi part), T[row][C..2C) = c' (xj part)
// H[b,i,c] = relu( a'[i,c] + max_{j in knn(i)} c'[j,c] )
__global__ __launch_bounds__(256) void edgemax(const float* __restrict__ T,
                                               const int* __restrict__ idx,
                                               float* __restrict__ H, int C) {
    __shared__ float sc[256][32];
    int b = blockIdx.x;
    int c0 = blockIdx.y * 32;
    int cc = threadIdx.x & 31;
    int i0 = threadIdx.x >> 5;
    const float* Tb = T + (size_t)b * 256 * 2 * C;

    for (int j = i0; j < 256; j += 8)
        sc[j][cc] = Tb[(size_t)j * 2 * C + C + c0 + cc];
    __syncthreads();

    for (int i = i0; i < 256; i += 8) {
        const int* ip = idx + ((size_t)b * 256 + i) * 16;
        float mx = -FLTMAX;
        #pragma unroll
        for (int k = 0; k < 16; ++k) {
            int j = ip[k];
            mx = fmaxf(mx, sc[j][cc]);
        }
        float a = Tb[(size_t)i * 2 * C + c0 + cc];
        H[((size_t)b * 256 + i) * C + c0 + cc] = fmaxf(a + mx, 0.0f);
    }
}

// ------------------------- head: pool + MLP -----------------------
__global__ __launch_bounds__(256) void finalk(const float* __restrict__ H3,
                                              const float* __restrict__ Wf1,
                                              const float* __restrict__ bf1,
                                              const float* __restrict__ gf,
                                              const float* __restrict__ bef,
                                              const float* __restrict__ Wf2,
                                              const float* __restrict__ bf2,
                                              float* __restrict__ out) {
    __shared__ float p[256];
    __shared__ float f1[128];
    int b = blockIdx.x, t = threadIdx.x;
    const float* Hb = H3 + (size_t)b * 256 * 256;
    float m = -FLTMAX;
    for (int i = 0; i < 256; i++) m = fmaxf(m, Hb[(size_t)i * 256 + t]);
    p[t] = m;
    __syncthreads();
    if (t < 128) {
        float acc = bf1[t];
        for (int k = 0; k < 256; k++) acc += p[k] * Wf1[k * 128 + t];
        f1[t] = fmaxf(gf[t] * (acc * BN_SCALE) + bef[t], 0.0f);
    }
    __syncthreads();
    if (t < 12) {
        float acc = bf2[t];
        for (int k = 0; k < 128; k++) acc += f1[k] * Wf2[k * 12 + t];
        out[b * 12 + t] = acc;
    }
}

// ------------------------- launch ---------------------------------
extern "C" void kernel_launch(void* const* d_in, const int* in_sizes, int n_in,
                              void* d_out, int out_size) {
    const float* x   = (const float*)d_in[0];
    const float* W1  = (const float*)d_in[1];
    const float* b1  = (const float*)d_in[2];
    const float* g1  = (const float*)d_in[3];
    const float* be1 = (const float*)d_in[4];
    const float* W2  = (const float*)d_in[5];
    const float* b2  = (const float*)d_in[6];
    const float* g2  = (const float*)d_in[7];
    const float* be2 = (const float*)d_in[8];
    const float* W3  = (const float*)d_in[9];
    const float* b3  = (const float*)d_in[10];
    const float* g3  = (const float*)d_in[11];
    const float* be3 = (const float*)d_in[12];
    const float* Wf1 = (const float*)d_in[13];
    const float* bf1 = (const float*)d_in[14];
    const float* gf  = (const float*)d_in[15];
    const float* bef = (const float*)d_in[16];
    const float* Wf2 = (const float*)d_in[17];
    const float* bf2 = (const float*)d_in[18];
    float* out = (float*)d_out;

    void *pT, *ph1, *ph2, *ph3, *pd2, *psq, *pidx;
    void *pW1p, *pb1p, *pW2p, *pb2p, *pW3p, *pb3p;
    cudaGetSymbolAddress(&pT,  g_T);
    cudaGetSymbolAddress(&ph1, g_h1);
    cudaGetSymbolAddress(&ph2, g_h2);
    cudaGetSymbolAddress(&ph3, g_h3);
    cudaGetSymbolAddress(&pd2, g_d2);
    cudaGetSymbolAddress(&psq, g_sq);
    cudaGetSymbolAddress(&pidx, g_idx);
    cudaGetSymbolAddress(&pW1p, g_W1p); cudaGetSymbolAddress(&pb1p, g_b1p);
    cudaGetSymbolAddress(&pW2p, g_W2p); cudaGetSymbolAddress(&pb2p, g_b2p);
    cudaGetSymbolAddress(&pW3p, g_W3p); cudaGetSymbolAddress(&pb3p, g_b3p);
    float* T   = (float*)pT;
    float* h1  = (float*)ph1;
    float* h2  = (float*)ph2;
    float* h3  = (float*)ph3;
    float* d2  = (float*)pd2;
    float* sq  = (float*)psq;
    int*   idx = (int*)pidx;

    // weight prep (tiny)
    prepw<<<8,   256>>>(W1, b1, g1, be1, (float*)pW1p, (float*)pb1p, 6,   64);
    prepw<<<64,  256>>>(W2, b2, g2, be2, (float*)pW2p, (float*)pb2p, 64,  128);
    prepw<<<256, 256>>>(W3, b3, g3, be3, (float*)pW3p, (float*)pb3p, 128, 256);

    // ---- layer 1 (D=6 -> C=64)
    rowsq<<<4096, 256>>>(x, sq, 6);
    gramd2<<<dim3(2, 2, 128), 256>>>(x, sq, d2, 6);
    topk16<<<128, 256>>>(d2, idx);
    sgemm<<<dim3(1, 256), 256>>>(x, (float*)pW1p, (float*)pb1p, T, 32768, 6, 128);
    edgemax<<<dim3(128, 2), 256>>>(T, idx, h1, 64);

    // ---- layer 2 (D=64 -> C=128)
    rowsq<<<4096, 256>>>(h1, sq, 64);
    gramd2<<<dim3(2, 2, 128), 256>>>(h1, sq, d2, 64);
    topk16<<<128, 256>>>(d2, idx);
    sgemm<<<dim3(2, 256), 256>>>(h1, (float*)pW2p, (float*)pb2p, T, 32768, 64, 256);
    edgemax<<<dim3(128, 4), 256>>>(T, idx, h2, 128);

    // ---- layer 3 (D=128 -> C=256)
    rowsq<<<4096, 256>>>(h2, sq, 128);
    gramd2<<<dim3(2, 2, 128), 256>>>(h2, sq, d2, 128);
    topk16<<<128, 256>>>(d2, idx);
    sgemm<<<dim3(4, 256), 256>>>(h2, (float*)pW3p, (float*)pb3p, T, 32768, 128, 512);
    edgemax<<<dim3(128, 8), 256>>>(T, idx, h3, 256);

    // ---- head
    finalk<<<128, 256>>>(h3, Wf1, bf1, gf, bef, Wf2, bf2, out);
}

// round 3
// speedup vs baseline: 1.1563x; 1.1563x over previous
#include <cuda_runtime.h>
#include <cstdint>

#define BN_SCALE 0.9999950000374997f
#define FLTMAX 3.402823466e+38f

// ------------------------- device scratch -------------------------
__device__ float g_T[32768 * 512];        // [a|c] buffer, reused across layers (64MB)
__device__ float g_h1[32768 * 64];
__device__ float g_h2[32768 * 128];
__device__ float g_h3[32768 * 256];
__device__ int   g_idx[128 * 256 * 16];
__device__ float g_W1p[6 * 128];   __device__ float g_b1p[128];
__device__ float g_W2p[64 * 256];  __device__ float g_b2p[256];
__device__ float g_W3p[128 * 512]; __device__ float g_b3p[512];

// ------------------------- weight prep ----------------------------
// Wp[k][c]      (c<C)  = alpha_c * (W[k][c] - W[Cin+k][c])      (xi coefficient)
// Wp[k][C+c]           = alpha_c * W[Cin+k][c]                  (xj coefficient)
// bp[c] = alpha_c*b[c] + be[c] (first half), 0 (second half); alpha = g*BN_SCALE
__global__ void prepw(const float* __restrict__ W, const float* __restrict__ b,
                      const float* __restrict__ g, const float* __restrict__ be,
                      float* __restrict__ Wp, float* __restrict__ bp,
                      int Cin, int C) {
    int n2 = 2 * C;
    int total = Cin * n2;
    for (int t = blockIdx.x * blockDim.x + threadIdx.x; t < total + n2;
         t += gridDim.x * blockDim.x) {
        if (t < total) {
            int k = t / n2, c = t % n2;
            float out;
            if (c < C) out = g[c] * BN_SCALE * (W[k * C + c] - W[(Cin + k) * C + c]);
            else { int cc = c - C; out = g[cc] * BN_SCALE * W[(Cin + k) * C + cc]; }
            Wp[t] = out;
        } else {
            int c = t - total;
            bp[c] = (c < C) ? (g[c] * BN_SCALE * b[c] + be[c]) : 0.0f;
        }
    }
}

// ------------------------- fused KNN, D=6 (layer 1) ---------------
// One block per batch; thread i owns row i. d2 = sq_i + sq_j - 2*dot (exact
// same formula shape as reference). Top-16 by insertion, strict '<' keeps
// the lowest index on ties (matches lax.top_k stability).
__global__ __launch_bounds__(256) void knn6(const float* __restrict__ X,
                                            int* __restrict__ idx) {
    __shared__ float pts[256][8];
    __shared__ float sqs[256];
    int b = blockIdx.x, i = threadIdx.x;
    const float* Xb = X + (size_t)b * 256 * 6;
    float xi[6];
    float s = 0.0f;
    #pragma unroll
    for (int k = 0; k < 6; k++) {
        float v = Xb[(size_t)i * 6 + k];
        xi[k] = v; pts[i][k] = v; s += v * v;
    }
    sqs[i] = s;
    __syncthreads();

    float bd[16]; int bi[16];
    #pragma unroll
    for (int t = 0; t < 16; t++) { bd[t] = FLTMAX; bi[t] = -1; }
    float sqi = s;
    for (int j = 0; j < 256; j++) {
        float dot = 0.0f;
        #pragma unroll
        for (int k = 0; k < 6; k++) dot += xi[k] * pts[j][k];
        float d = sqi + sqs[j] - 2.0f * dot;
        if (j == i) d = FLTMAX;
        if (d < bd[15]) {
            bd[15] = d; bi[15] = j;
            #pragma unroll
            for (int t = 15; t > 0; --t) {
                if (bd[t] < bd[t - 1]) {
                    float td = bd[t]; bd[t] = bd[t - 1]; bd[t - 1] = td;
                    int ti = bi[t];   bi[t] = bi[t - 1]; bi[t - 1] = ti;
                }
            }
        }
    }
    int* op = idx + ((size_t)b * 256 + i) * 16;
    #pragma unroll
    for (int t = 0; t < 16; t++) op[t] = bi[t];
}

// ------------------------- fused KNN, D in {64,128} ---------------
// Block: batch b (blockIdx.y), row-quarter q (blockIdx.x, 64 rows).
// GEMM phase: 64x256 Gram tile, 8x4 thread tile, double-buffered smem.
// Then d2 into smem, then 64 threads do top-16 insertion per row.
// Dynamic smem layout (floats): sqs[256] | As[2][16][68] | Bs[2][16][132] | ds[64][260]
template<int D>
__global__ __launch_bounds__(256) void knnf(const float* __restrict__ H,
                                            int* __restrict__ idx) {
    extern __shared__ float sm[];
    float* sqs = sm;                 // 256
    float* As  = sm + 256;           // 2*16*68  = 2176
    float* Bs  = sm + 256 + 2176;    // 2*16*132 = 4224
    float* ds  = sm + 256 + 2176 + 4224; // 64*260 = 16640
    int b = blockIdx.y;
    int i0 = blockIdx.x * 64;
    const float* Hb = H + (size_t)b * 256 * D;
    int tid = threadIdx.x;
    int ty = tid >> 5, tx = tid & 31;

    // sum of squares for all 256 batch rows
    {
        const float4* rp = (const float4*)(Hb + (size_t)tid * D);
        float s = 0.0f;
        #pragma unroll
        for (int u = 0; u < D / 4; ++u) {
            float4 v = rp[u];
            s += v.x * v.x + v.y * v.y + v.z * v.z + v.w * v.w;
        }
        sqs[tid] = s;
    }

    int ar = tid & 63,  ak4 = (tid >> 6) * 4;   // A stage: row ar, k-offset ak4 (float4)
    int br = tid & 127, bk8 = (tid >> 7) * 8;   // B stage: row br, k-offsets bk8, bk8+4

    for (int h = 0; h < 2; ++h) {
        int j0 = h * 128;
        float acc[8][4];
        #pragma unroll
        for (int r = 0; r < 8; r++)
            #pragma unroll
            for (int s = 0; s < 4; s++) acc[r][s] = 0.0f;

        float4 pa  = *(const float4*)(Hb + (size_t)(i0 + ar) * D + ak4);
        float4 pb0 = *(const float4*)(Hb + (size_t)(j0 + br) * D + bk8);
        float4 pb1 = *(const float4*)(Hb + (size_t)(j0 + br) * D + bk8 + 4);
        int buf = 0;

        for (int k0 = 0; k0 < D; k0 += 16) {
            float* Ab = As + buf * 1088;
            float* Bb = Bs + buf * 2112;
            Ab[(ak4 + 0) * 68 + ar] = pa.x;
            Ab[(ak4 + 1) * 68 + ar] = pa.y;
            Ab[(ak4 + 2) * 68 + ar] = pa.z;
            Ab[(ak4 + 3) * 68 + ar] = pa.w;
            Bb[(bk8 + 0) * 132 + br] = pb0.x;
            Bb[(bk8 + 1) * 132 + br] = pb0.y;
            Bb[(bk8 + 2) * 132 + br] = pb0.z;
            Bb[(bk8 + 3) * 132 + br] = pb0.w;
            Bb[(bk8 + 4) * 132 + br] = pb1.x;
            Bb[(bk8 + 5) * 132 + br] = pb1.y;
            Bb[(bk8 + 6) * 132 + br] = pb1.z;
            Bb[(bk8 + 7) * 132 + br] = pb1.w;
            __syncthreads();
            if (k0 + 16 < D) {
                pa  = *(const float4*)(Hb + (size_t)(i0 + ar) * D + k0 + 16 + ak4);
                pb0 = *(const float4*)(Hb + (size_t)(j0 + br) * D + k0 + 16 + bk8);
                pb1 = *(const float4*)(Hb + (size_t)(j0 + br) * D + k0 + 16 + bk8 + 4);
            }
            #pragma unroll
            for (int kk = 0; kk < 16; ++kk) {
                float a[8];
                *(float4*)&a[0] = *(const float4*)&Ab[kk * 68 + ty * 8];
                *(float4*)&a[4] = *(const float4*)&Ab[kk * 68 + ty * 8 + 4];
                float4 bv = *(const float4*)&Bb[kk * 132 + tx * 4];
                #pragma unroll
                for (int r = 0; r < 8; r++) {
                    acc[r][0] += a[r] * bv.x;
                    acc[r][1] += a[r] * bv.y;
                    acc[r][2] += a[r] * bv.z;
                    acc[r][3] += a[r] * bv.w;
                }
            }
            buf ^= 1;
        }

        // d2 tile -> smem
        #pragma unroll
        for (int r = 0; r < 8; r++) {
            int row = ty * 8 + r;
            float si = sqs[i0 + row];
            float4 v;
            int col = j0 + tx * 4;
            v.x = si + sqs[col + 0] - 2.0f * acc[r][0];
            v.y = si + sqs[col + 1] - 2.0f * acc[r][1];
            v.z = si + sqs[col + 2] - 2.0f * acc[r][2];
            v.w = si + sqs[col + 3] - 2.0f * acc[r][3];
            int gi = i0 + row;
            if (gi == col + 0) v.x = FLTMAX;
            if (gi == col + 1) v.y = FLTMAX;
            if (gi == col + 2) v.z = FLTMAX;
            if (gi == col + 3) v.w = FLTMAX;
            *(float4*)&ds[row * 260 + col] = v;
        }
    }
    __syncthreads();

    // top-16 per row (threads 0..63)
    if (tid < 64) {
        const float* dr = &ds[tid * 260];
        float bd[16]; int bi[16];
        #pragma unroll
        for (int t = 0; t < 16; t++) { bd[t] = FLTMAX; bi[t] = -1; }
        for (int j = 0; j < 256; j++) {
            float d = dr[j];
            if (d < bd[15]) {
                bd[15] = d; bi[15] = j;
                #pragma unroll
                for (int t = 15; t > 0; --t) {
                    if (bd[t] < bd[t - 1]) {
                        float td = bd[t]; bd[t] = bd[t - 1]; bd[t - 1] = td;
                        int ti = bi[t];   bi[t] = bi[t - 1]; bi[t - 1] = ti;
                    }
                }
            }
        }
        int* op = idx + ((size_t)b * 256 + i0 + tid) * 16;
        #pragma unroll
        for (int t = 0; t < 16; t++) op[t] = bi[t];
    }
}

// ------------------------- layer-1 SGEMM (K=6, N=128) -------------
// Memory-bound: warp per row, weights in smem, float4 stores.
__global__ __launch_bounds__(256) void sgemm6(const float* __restrict__ X,
                                              const float* __restrict__ Wp,
                                              const float* __restrict__ bp,
                                              float* __restrict__ T) {
    __shared__ float Ws[6][128];
    __shared__ float bs[128];
    int tid = threadIdx.x;
    if (tid < 128) bs[tid] = bp[tid];
    for (int t = tid; t < 768; t += 256) Ws[t / 128][t % 128] = Wp[t];
    __syncthreads();
    int warp = tid >> 5, lane = tid & 31;
    int row = blockIdx.x * 8 + warp;
    const float* xr = X + (size_t)row * 6;
    float x0 = xr[0], x1 = xr[1], x2 = xr[2], x3 = xr[3], x4 = xr[4], x5 = xr[5];
    int c = lane * 4;
    float4 o;
    #pragma unroll
    for (int u = 0; u < 4; ++u) {
        float v = bs[c + u];
        v += x0 * Ws[0][c + u]; v += x1 * Ws[1][c + u]; v += x2 * Ws[2][c + u];
        v += x3 * Ws[3][c + u]; v += x4 * Ws[4][c + u]; v += x5 * Ws[5][c + u];
        ((float*)&o)[u] = v;
    }
    *(float4*)&T[(size_t)row * 128 + c] = o;
}

// ------------------------- main SGEMM (A[MxK] @ W[KxN] + bias) ----
// 128x128 tile, 8x8 register blocking, register-prefetch pipeline.
__global__ __launch_bounds__(256) void sgemm(const float* __restrict__ A,
                                             const float* __restrict__ W,
                                             const float* __restrict__ bias,
                                             float* __restrict__ C,
                                             int M, int K, int N) {
    __shared__ __align__(16) float As[16][132];
    __shared__ __align__(16) float Bs[16][132];
    int i0 = blockIdx.y * 128;
    int j0 = blockIdx.x * 128;
    int tid = threadIdx.x;
    int tx = tid & 15, ty = tid >> 4;
    int lka = tid & 15, lia = tid >> 4;
    int ljb = tid & 127, lkb = tid >> 7;

    float acc[8][8];
    #pragma unroll
    for (int r = 0; r < 8; r++)
        #pragma unroll
        for (int s = 0; s < 8; s++) acc[r][s] = 0.0f;

    float pa[8], pb[8];
    #pragma unroll
    for (int it = 0; it < 8; ++it) {
        pa[it] = (lka < K) ? A[(size_t)(i0 + lia + it * 16) * K + lka] : 0.0f;
        int kb = lkb + it * 2;
        pb[it] = (kb < K) ? W[(size_t)kb * N + j0 + ljb] : 0.0f;
    }

    for (int k0 = 0; k0 < K; k0 += 16) {
        #pragma unroll
        for (int it = 0; it < 8; ++it) {
            As[lka][lia + it * 16] = pa[it];
            Bs[lkb + it * 2][ljb] = pb[it];
        }
        __syncthreads();
        if (k0 + 16 < K) {
            #pragma unroll
            for (int it = 0; it < 8; ++it) {
                int ka = k0 + 16 + lka;
                pa[it] = (ka < K) ? A[(size_t)(i0 + lia + it * 16) * K + ka] : 0.0f;
                int kb = k0 + 16 + lkb + it * 2;
                pb[it] = (kb < K) ? W[(size_t)kb * N + j0 + ljb] : 0.0f;
            }
        }
        #pragma unroll
        for (int kk = 0; kk < 16; ++kk) {
            float a[8], bb[8];
            *(float4*)&a[0]  = *(const float4*)&As[kk][ty * 8];
            *(float4*)&a[4]  = *(const float4*)&As[kk][ty * 8 + 4];
            *(float4*)&bb[0] = *(const float4*)&Bs[kk][tx * 8];
            *(float4*)&bb[4] = *(const float4*)&Bs[kk][tx * 8 + 4];
            #pragma unroll
            for (int r = 0; r < 8; r++)
                #pragma unroll
                for (int s = 0; s < 8; s++) acc[r][s] += a[r] * bb[s];
        }
        __syncthreads();
    }

    #pragma unroll
    for (int r = 0; r < 8; r++) {
        int row = i0 + ty * 8 + r;
        #pragma unroll
        for (int s = 0; s < 8; s += 4) {
            int col = j0 + tx * 8 + s;
            float4 v;
            v.x = acc[r][s + 0] + bias[col + 0];
            v.y = acc[r][s + 1] + bias[col + 1];
            v.z = acc[r][s + 2] + bias[col + 2];
            v.w = acc[r][s + 3] + bias[col + 3];
            *(float4*)&C[(size_t)row * N + col] = v;
        }
    }
}

// ------------------------- edge max -------------------------------
// T[row][0..C) = a' (affine-folded xi part), T[row][C..2C) = c' (xj part)
// H[b,i,c] = relu( a'[i,c] + max_{j in knn(i)} c'[j,c] )
__global__ __launch_bounds__(256) void edgemax(const float* __restrict__ T,
                                               const int* __restrict__ idx,
                                               float* __restrict__ H, int C) {
    __shared__ float sc[256][32];
    int b = blockIdx.x;
    int c0 = blockIdx.y * 32;
    int cc = threadIdx.x & 31;
    int i0 = threadIdx.x >> 5;
    const float* Tb = T + (size_t)b * 256 * 2 * C;

    for (int j = i0; j < 256; j += 8)
        sc[j][cc] = Tb[(size_t)j * 2 * C + C + c0 + cc];
    __syncthreads();

    for (int i = i0; i < 256; i += 8) {
        const int* ip = idx + ((size_t)b * 256 + i) * 16;
        float mx = -FLTMAX;
        #pragma unroll
        for (int k = 0; k < 16; ++k) {
            int j = ip[k];
            mx = fmaxf(mx, sc[j][cc]);
        }
        float a = Tb[(size_t)i * 2 * C + c0 + cc];
        H[((size_t)b * 256 + i) * C + c0 + cc] = fmaxf(a + mx, 0.0f);
    }
}

// ------------------------- head: pool + MLP -----------------------
__global__ __launch_bounds__(256) void finalk(const float* __restrict__ H3,
                                              const float* __restrict__ Wf1,
                                              const float* __restrict__ bf1,
                                              const float* __restrict__ gf,
                                              const float* __restrict__ bef,
                                              const float* __restrict__ Wf2,
                                              const float* __restrict__ bf2,
                                              float* __restrict__ out) {
    __shared__ float p[256];
    __shared__ float f1[128];
    int b = blockIdx.x, t = threadIdx.x;
    const float* Hb = H3 + (size_t)b * 256 * 256;
    float m = -FLTMAX;
    for (int i = 0; i < 256; i++) m = fmaxf(m, Hb[(size_t)i * 256 + t]);
    p[t] = m;
    __syncthreads();
    if (t < 128) {
        float acc = bf1[t];
        for (int k = 0; k < 256; k++) acc += p[k] * Wf1[k * 128 + t];
        f1[t] = fmaxf(gf[t] * (acc * BN_SCALE) + bef[t], 0.0f);
    }
    __syncthreads();
    if (t < 12) {
        float acc = bf2[t];
        for (int k = 0; k < 128; k++) acc += f1[k] * Wf2[k * 12 + t];
        out[b * 12 + t] = acc;
    }
}

// ------------------------- launch ---------------------------------
static const int KNNF_SMEM = (256 + 2176 + 4224 + 16640) * 4;  // 93,184 bytes

extern "C" void kernel_launch(void* const* d_in, const int* in_sizes, int n_in,
                              void* d_out, int out_size) {
    const float* x   = (const float*)d_in[0];
    const float* W1  = (const float*)d_in[1];
    const float* b1  = (const float*)d_in[2];
    const float* g1  = (const float*)d_in[3];
    const float* be1 = (const float*)d_in[4];
    const float* W2  = (const float*)d_in[5];
    const float* b2  = (const float*)d_in[6];
    const float* g2  = (const float*)d_in[7];
    const float* be2 = (const float*)d_in[8];
    const float* W3  = (const float*)d_in[9];
    const float* b3  = (const float*)d_in[10];
    const float* g3  = (const float*)d_in[11];
    const float* be3 = (const float*)d_in[12];
    const float* Wf1 = (const float*)d_in[13];
    const float* bf1 = (const float*)d_in[14];
    const float* gf  = (const float*)d_in[15];
    const float* bef = (const float*)d_in[16];
    const float* Wf2 = (const float*)d_in[17];
    const float* bf2 = (const float*)d_in[18];
    float* out = (float*)d_out;

    cudaFuncSetAttribute(knnf<64>,  cudaFuncAttributeMaxDynamicSharedMemorySize, KNNF_SMEM);
    cudaFuncSetAttribute(knnf<128>, cudaFuncAttributeMaxDynamicSharedMemorySize, KNNF_SMEM);

    void *pT, *ph1, *ph2, *ph3, *pidx;
    void *pW1p, *pb1p, *pW2p, *pb2p, *pW3p, *pb3p;
    cudaGetSymbolAddress(&pT,  g_T);
    cudaGetSymbolAddress(&ph1, g_h1);
    cudaGetSymbolAddress(&ph2, g_h2);
    cudaGetSymbolAddress(&ph3, g_h3);
    cudaGetSymbolAddress(&pidx, g_idx);
    cudaGetSymbolAddress(&pW1p, g_W1p); cudaGetSymbolAddress(&pb1p, g_b1p);
    cudaGetSymbolAddress(&pW2p, g_W2p); cudaGetSymbolAddress(&pb2p, g_b2p);
    cudaGetSymbolAddress(&pW3p, g_W3p); cudaGetSymbolAddress(&pb3p, g_b3p);
    float* T   = (float*)pT;
    float* h1  = (float*)ph1;
    float* h2  = (float*)ph2;
    float* h3  = (float*)ph3;
    int*   idx = (int*)pidx;

    // weight prep (tiny)
    prepw<<<8,   256>>>(W1, b1, g1, be1, (float*)pW1p, (float*)pb1p, 6,   64);
    prepw<<<64,  256>>>(W2, b2, g2, be2, (float*)pW2p, (float*)pb2p, 64,  128);
    prepw<<<256, 256>>>(W3, b3, g3, be3, (float*)pW3p, (float*)pb3p, 128, 256);

    // ---- layer 1 (D=6 -> C=64)
    knn6<<<128, 256>>>(x, idx);
    sgemm6<<<4096, 256>>>(x, (float*)pW1p, (float*)pb1p, T);
    edgemax<<<dim3(128, 2), 256>>>(T, idx, h1, 64);

    // ---- layer 2 (D=64 -> C=128)
    knnf<64><<<dim3(4, 128), 256, KNNF_SMEM>>>(h1, idx);
    sgemm<<<dim3(2, 256), 256>>>(h1, (float*)pW2p, (float*)pb2p, T, 32768, 64, 256);
    edgemax<<<dim3(128, 4), 256>>>(T, idx, h2, 128);

    // ---- layer 3 (D=128 -> C=256)
    knnf<128><<<dim3(4, 128), 256, KNNF_SMEM>>>(h2, idx);
    sgemm<<<dim3(4, 256), 256>>>(h2, (float*)pW3p, (float*)pb3p, T, 32768, 128, 512);
    edgemax<<<dim3(128, 8), 256>>>(T, idx, h3, 256);

    // ---- head
    finalk<<<128, 256>>>(h3, Wf1, bf1, gf, bef, Wf2, bf2, out);
}

// round 4
// speedup vs baseline: 1.1717x; 1.0133x over previous
#include <cuda_runtime.h>
#include <cstdint>

#define BN_SCALE 0.9999950000374997f
#define FLTMAX 3.402823466e+38f

typedef unsigned long long u64;

// packed fp32x2 helpers (sm_100+: fma.rn.f32x2) — bit-exact fp32 per lane
__device__ __forceinline__ u64 pk2(float v) {
    u64 r; asm("mov.b64 %0,{%1,%1};" : "=l"(r) : "f"(v)); return r;
}
__device__ __forceinline__ void fma2(u64& d, u64 a, u64 b) {
    asm("fma.rn.f32x2 %0,%1,%2,%0;" : "+l"(d) : "l"(a), "l"(b));
}
__device__ __forceinline__ float2 unpk(u64 v) {
    float2 r; asm("mov.b64 {%0,%1},%2;" : "=f"(r.x), "=f"(r.y) : "l"(v)); return r;
}

// ------------------------- device scratch -------------------------
__device__ float g_T[32768 * 512];
__device__ float g_h1[32768 * 64];
__device__ float g_h2[32768 * 128];
__device__ float g_h3[32768 * 256];
__device__ int   g_idx[128 * 256 * 16];
__device__ float g_W1p[6 * 128];   __device__ float g_b1p[128];
__device__ float g_W2p[64 * 256];  __device__ float g_b2p[256];
__device__ float g_W3p[128 * 512]; __device__ float g_b3p[512];

// ------------------------- weight prep ----------------------------
__global__ void prepw(const float* __restrict__ W, const float* __restrict__ b,
                      const float* __restrict__ g, const float* __restrict__ be,
                      float* __restrict__ Wp, float* __restrict__ bp,
                      int Cin, int C) {
    int n2 = 2 * C;
    int total = Cin * n2;
    for (int t = blockIdx.x * blockDim.x + threadIdx.x; t < total + n2;
         t += gridDim.x * blockDim.x) {
        if (t < total) {
            int k = t / n2, c = t % n2;
            float out;
            if (c < C) out = g[c] * BN_SCALE * (W[k * C + c] - W[(Cin + k) * C + c]);
            else { int cc = c - C; out = g[cc] * BN_SCALE * W[(Cin + k) * C + cc]; }
            Wp[t] = out;
        } else {
            int c = t - total;
            bp[c] = (c < C) ? (g[c] * BN_SCALE * b[c] + be[c]) : 0.0f;
        }
    }
}

// ------------------------- fused KNN, D=6 (layer 1) ---------------
// 512 threads: row i handled by threads i (j in [0,128)) and i+256 (j in [128,256)).
// Each keeps a sorted top-16 via strict-'<' insertion; owner merges partner's
// sorted list by re-insertion (identical tie semantics: lower j wins).
__global__ __launch_bounds__(512) void knn6(const float* __restrict__ X,
                                            int* __restrict__ idx) {
    __shared__ float pts[256][8];
    __shared__ float sqs[256];
    __shared__ float od[256][16];
    __shared__ int   oi[256][16];
    int b = blockIdx.x, tid = threadIdx.x;
    int i = tid & 255;
    int half = tid >> 8;                  // 0: j in [0,128), 1: j in [128,256)
    const float* Xb = X + (size_t)b * 256 * 6;

    if (tid < 256) {
        float s = 0.0f;
        #pragma unroll
        for (int k = 0; k < 6; k++) {
            float v = Xb[(size_t)i * 6 + k];
            pts[i][k] = v; s += v * v;
        }
        sqs[i] = s;
    }
    __syncthreads();

    float xi[6];
    #pragma unroll
    for (int k = 0; k < 6; k++) xi[k] = pts[i][k];
    float sqi = sqs[i];

    float bd[16]; int bi[16];
    #pragma unroll
    for (int t = 0; t < 16; t++) { bd[t] = FLTMAX; bi[t] = -1; }

    int j0 = half * 128;
    for (int jj = 0; jj < 128; jj++) {
        int j = j0 + jj;
        float dot = 0.0f;
        #pragma unroll
        for (int k = 0; k < 6; k++) dot += xi[k] * pts[j][k];
        float d = sqi + sqs[j] - 2.0f * dot;
        if (j == i) d = FLTMAX;
        if (d < bd[15]) {
            bd[15] = d; bi[15] = j;
            #pragma unroll
            for (int t = 15; t > 0; --t) {
                if (bd[t] < bd[t - 1]) {
                    float td = bd[t]; bd[t] = bd[t - 1]; bd[t - 1] = td;
                    int ti = bi[t];   bi[t] = bi[t - 1]; bi[t - 1] = ti;
                }
            }
        }
    }

    if (half == 1) {
        #pragma unroll
        for (int t = 0; t < 16; t++) { od[i][t] = bd[t]; oi[i][t] = bi[t]; }
    }
    __syncthreads();

    if (half == 0) {
        // merge partner's sorted ascending list by re-insertion (strict '<')
        #pragma unroll
        for (int t = 0; t < 16; t++) {
            float d = od[i][t]; int j = oi[i][t];
            if (d < bd[15]) {
                bd[15] = d; bi[15] = j;
                #pragma unroll
                for (int u = 15; u > 0; --u) {
                    if (bd[u] < bd[u - 1]) {
                        float td = bd[u]; bd[u] = bd[u - 1]; bd[u - 1] = td;
                        int ti = bi[u];   bi[u] = bi[u - 1]; bi[u - 1] = ti;
                    }
                }
            }
        }
        int* op = idx + ((size_t)b * 256 + i) * 16;
        #pragma unroll
        for (int t = 0; t < 16; t++) op[t] = bi[t];
    }
}

// ------------------------- fused KNN, D in {64,128} ---------------
// Gram phase with FFMA2: acc pairs over adjacent rows (free from LDS.128),
// B operand duplicated via mov.b64.
template<int D>
__global__ __launch_bounds__(256) void knnf(const float* __restrict__ H,
                                            int* __restrict__ idx) {
    extern __shared__ float sm[];
    float* sqs = sm;                 // 256
    float* As  = sm + 256;           // 2*16*68  = 2176
    float* Bs  = sm + 256 + 2176;    // 2*16*132 = 4224
    float* ds  = sm + 256 + 2176 + 4224; // 64*260 = 16640
    int b = blockIdx.y;
    int i0 = blockIdx.x * 64;
    const float* Hb = H + (size_t)b * 256 * D;
    int tid = threadIdx.x;
    int ty = tid >> 5, tx = tid & 31;

    {
        const float4* rp = (const float4*)(Hb + (size_t)tid * D);
        float s = 0.0f;
        #pragma unroll
        for (int u = 0; u < D / 4; ++u) {
            float4 v = rp[u];
            s += v.x * v.x + v.y * v.y + v.z * v.z + v.w * v.w;
        }
        sqs[tid] = s;
    }

    int ar = tid & 63,  ak4 = (tid >> 6) * 4;
    int br = tid & 127, bk8 = (tid >> 7) * 8;

    for (int h = 0; h < 2; ++h) {
        int j0 = h * 128;
        u64 acc2[4][4];              // row-pairs (ty*8+2p, +2p+1) x 4 cols
        #pragma unroll
        for (int p = 0; p < 4; p++)
            #pragma unroll
            for (int s = 0; s < 4; s++) acc2[p][s] = 0ull;

        float4 pa  = *(const float4*)(Hb + (size_t)(i0 + ar) * D + ak4);
        float4 pb0 = *(const float4*)(Hb + (size_t)(j0 + br) * D + bk8);
        float4 pb1 = *(const float4*)(Hb + (size_t)(j0 + br) * D + bk8 + 4);
        int buf = 0;

        for (int k0 = 0; k0 < D; k0 += 16) {
            float* Ab = As + buf * 1088;
            float* Bb = Bs + buf * 2112;
            Ab[(ak4 + 0) * 68 + ar] = pa.x;
            Ab[(ak4 + 1) * 68 + ar] = pa.y;
            Ab[(ak4 + 2) * 68 + ar] = pa.z;
            Ab[(ak4 + 3) * 68 + ar] = pa.w;
            Bb[(bk8 + 0) * 132 + br] = pb0.x;
            Bb[(bk8 + 1) * 132 + br] = pb0.y;
            Bb[(bk8 + 2) * 132 + br] = pb0.z;
            Bb[(bk8 + 3) * 132 + br] = pb0.w;
            Bb[(bk8 + 4) * 132 + br] = pb1.x;
            Bb[(bk8 + 5) * 132 + br] = pb1.y;
            Bb[(bk8 + 6) * 132 + br] = pb1.z;
            Bb[(bk8 + 7) * 132 + br] = pb1.w;
            __syncthreads();
            if (k0 + 16 < D) {
                pa  = *(const float4*)(Hb + (size_t)(i0 + ar) * D + k0 + 16 + ak4);
                pb0 = *(const float4*)(Hb + (size_t)(j0 + br) * D + k0 + 16 + bk8);
                pb1 = *(const float4*)(Hb + (size_t)(j0 + br) * D + k0 + 16 + bk8 + 4);
            }
            #pragma unroll
            for (int kk = 0; kk < 16; ++kk) {
                float4 a0 = *(const float4*)&Ab[kk * 68 + ty * 8];
                float4 a1 = *(const float4*)&Ab[kk * 68 + ty * 8 + 4];
                u64 ap[4];
                ap[0] = ((const u64*)&a0)[0]; ap[1] = ((const u64*)&a0)[1];
                ap[2] = ((const u64*)&a1)[0]; ap[3] = ((const u64*)&a1)[1];
                float4 bv = *(const float4*)&Bb[kk * 132 + tx * 4];
                u64 bd0 = pk2(bv.x), bd1 = pk2(bv.y), bd2 = pk2(bv.z), bd3 = pk2(bv.w);
                #pragma unroll
                for (int p = 0; p < 4; p++) {
                    fma2(acc2[p][0], ap[p], bd0);
                    fma2(acc2[p][1], ap[p], bd1);
                    fma2(acc2[p][2], ap[p], bd2);
                    fma2(acc2[p][3], ap[p], bd3);
                }
            }
            buf ^= 1;
        }

        // d2 tile -> smem (unpack row pairs)
        #pragma unroll
        for (int p = 0; p < 4; p++) {
            float2 c0 = unpk(acc2[p][0]);
            float2 c1 = unpk(acc2[p][1]);
            float2 c2 = unpk(acc2[p][2]);
            float2 c3 = unpk(acc2[p][3]);
            int col = j0 + tx * 4;
            #pragma unroll
            for (int e = 0; e < 2; e++) {
                int row = ty * 8 + 2 * p + e;
                float si = sqs[i0 + row];
                float d0 = (e == 0) ? c0.x : c0.y;
                float d1 = (e == 0) ? c1.x : c1.y;
                float d2_ = (e == 0) ? c2.x : c2.y;
                float d3 = (e == 0) ? c3.x : c3.y;
                float4 v;
                v.x = si + sqs[col + 0] - 2.0f * d0;
                v.y = si + sqs[col + 1] - 2.0f * d1;
                v.z = si + sqs[col + 2] - 2.0f * d2_;
                v.w = si + sqs[col + 3] - 2.0f * d3;
                int gi = i0 + row;
                if (gi == col + 0) v.x = FLTMAX;
                if (gi == col + 1) v.y = FLTMAX;
                if (gi == col + 2) v.z = FLTMAX;
                if (gi == col + 3) v.w = FLTMAX;
                *(float4*)&ds[row * 260 + col] = v;
            }
        }
    }
    __syncthreads();

    if (tid < 64) {
        const float* dr = &ds[tid * 260];
        float bd[16]; int bi[16];
        #pragma unroll
        for (int t = 0; t < 16; t++) { bd[t] = FLTMAX; bi[t] = -1; }
        for (int j = 0; j < 256; j++) {
            float d = dr[j];
            if (d < bd[15]) {
                bd[15] = d; bi[15] = j;
                #pragma unroll
                for (int t = 15; t > 0; --t) {
                    if (bd[t] < bd[t - 1]) {
                        float td = bd[t]; bd[t] = bd[t - 1]; bd[t - 1] = td;
                        int ti = bi[t];   bi[t] = bi[t - 1]; bi[t - 1] = ti;
                    }
                }
            }
        }
        int* op = idx + ((size_t)b * 256 + i0 + tid) * 16;
        #pragma unroll
        for (int t = 0; t < 16; t++) op[t] = bi[t];
    }
}

// ------------------------- layer-1 SGEMM (K=6, N=128) -------------
__global__ __launch_bounds__(256) void sgemm6(const float* __restrict__ X,
                                              const float* __restrict__ Wp,
                                              const float* __restrict__ bp,
                                              float* __restrict__ T) {
    __shared__ float Ws[6][128];
    __shared__ float bs[128];
    int tid = threadIdx.x;
    if (tid < 128) bs[tid] = bp[tid];
    for (int t = tid; t < 768; t += 256) Ws[t / 128][t % 128] = Wp[t];
    __syncthreads();
    int warp = tid >> 5, lane = tid & 31;
    int row = blockIdx.x * 8 + warp;
    const float* xr = X + (size_t)row * 6;
    float x0 = xr[0], x1 = xr[1], x2 = xr[2], x3 = xr[3], x4 = xr[4], x5 = xr[5];
    int c = lane * 4;
    float4 o;
    #pragma unroll
    for (int u = 0; u < 4; ++u) {
        float v = bs[c + u];
        v += x0 * Ws[0][c + u]; v += x1 * Ws[1][c + u]; v += x2 * Ws[2][c + u];
        v += x3 * Ws[3][c + u]; v += x4 * Ws[4][c + u]; v += x5 * Ws[5][c + u];
        ((float*)&o)[u] = v;
    }
    *(float4*)&T[(size_t)row * 128 + c] = o;
}

// ------------------------- main SGEMM (FFMA2 inner loop) ----------
__global__ __launch_bounds__(256) void sgemm(const float* __restrict__ A,
                                             const float* __restrict__ W,
                                             const float* __restrict__ bias,
                                             float* __restrict__ C,
                                             int M, int K, int N) {
    __shared__ __align__(16) float As[16][132];
    __shared__ __align__(16) float Bs[16][132];
    int i0 = blockIdx.y * 128;
    int j0 = blockIdx.x * 128;
    int tid = threadIdx.x;
    int tx = tid & 15, ty = tid >> 4;
    int lka = tid & 15, lia = tid >> 4;
    int ljb = tid & 127, lkb = tid >> 7;

    u64 acc2[4][8];                  // row-pairs (ty*8+2p, +2p+1) x 8 cols
    #pragma unroll
    for (int p = 0; p < 4; p++)
        #pragma unroll
        for (int s = 0; s < 8; s++) acc2[p][s] = 0ull;

    float pa[8], pb[8];
    #pragma unroll
    for (int it = 0; it < 8; ++it) {
        pa[it] = (lka < K) ? A[(size_t)(i0 + lia + it * 16) * K + lka] : 0.0f;
        int kb = lkb + it * 2;
        pb[it] = (kb < K) ? W[(size_t)kb * N + j0 + ljb] : 0.0f;
    }

    for (int k0 = 0; k0 < K; k0 += 16) {
        #pragma unroll
        for (int it = 0; it < 8; ++it) {
            As[lka][lia + it * 16] = pa[it];
            Bs[lkb + it * 2][ljb] = pb[it];
        }
        __syncthreads();
        if (k0 + 16 < K) {
            #pragma unroll
            for (int it = 0; it < 8; ++it) {
                int ka = k0 + 16 + lka;
                pa[it] = (ka < K) ? A[(size_t)(i0 + lia + it * 16) * K + ka] : 0.0f;
                int kb = k0 + 16 + lkb + it * 2;
                pb[it] = (kb < K) ? W[(size_t)kb * N + j0 + ljb] : 0.0f;
            }
        }
        #pragma unroll
        for (int kk = 0; kk < 16; ++kk) {
            float4 a0 = *(const float4*)&As[kk][ty * 8];
            float4 a1 = *(const float4*)&As[kk][ty * 8 + 4];
            u64 ap[4];
            ap[0] = ((const u64*)&a0)[0]; ap[1] = ((const u64*)&a0)[1];
            ap[2] = ((const u64*)&a1)[0]; ap[3] = ((const u64*)&a1)[1];
            float4 b0 = *(const float4*)&Bs[kk][tx * 8];
            float4 b1 = *(const float4*)&Bs[kk][tx * 8 + 4];
            u64 bd_[8];
            bd_[0] = pk2(b0.x); bd_[1] = pk2(b0.y); bd_[2] = pk2(b0.z); bd_[3] = pk2(b0.w);
            bd_[4] = pk2(b1.x); bd_[5] = pk2(b1.y); bd_[6] = pk2(b1.z); bd_[7] = pk2(b1.w);
            #pragma unroll
            for (int p = 0; p < 4; p++)
                #pragma unroll
                for (int s = 0; s < 8; s++)
                    fma2(acc2[p][s], ap[p], bd_[s]);
        }
        __syncthreads();
    }

    #pragma unroll
    for (int p = 0; p < 4; p++) {
        float2 c[8];
        #pragma unroll
        for (int s = 0; s < 8; s++) c[s] = unpk(acc2[p][s]);
        #pragma unroll
        for (int e = 0; e < 2; e++) {
            int row = i0 + ty * 8 + 2 * p + e;
            #pragma unroll
            for (int s = 0; s < 8; s += 4) {
                int col = j0 + tx * 8 + s;
                float4 v;
                v.x = ((e == 0) ? c[s + 0].x : c[s + 0].y) + bias[col + 0];
                v.y = ((e == 0) ? c[s + 1].x : c[s + 1].y) + bias[col + 1];
                v.z = ((e == 0) ? c[s + 2].x : c[s + 2].y) + bias[col + 2];
                v.w = ((e == 0) ? c[s + 3].x : c[s + 3].y) + bias[col + 3];
                *(float4*)&C[(size_t)row * N + col] = v;
            }
        }
    }
}

// ------------------------- edge max -------------------------------
__global__ __launch_bounds__(256) void edgemax(const float* __restrict__ T,
                                               const int* __restrict__ idx,
                                               float* __restrict__ H, int C) {
    __shared__ float sc[256][32];
    int b = blockIdx.x;
    int c0 = blockIdx.y * 32;
    int cc = threadIdx.x & 31;
    int i0 = threadIdx.x >> 5;
    const float* Tb = T + (size_t)b * 256 * 2 * C;

    for (int j = i0; j < 256; j += 8)
        sc[j][cc] = Tb[(size_t)j * 2 * C + C + c0 + cc];
    __syncthreads();

    for (int i = i0; i < 256; i += 8) {
        const int* ip = idx + ((size_t)b * 256 + i) * 16;
        float mx = -FLTMAX;
        #pragma unroll
        for (int k = 0; k < 16; ++k) {
            int j = ip[k];
            mx = fmaxf(mx, sc[j][cc]);
        }
        float a = Tb[(size_t)i * 2 * C + c0 + cc];
        H[((size_t)b * 256 + i) * C + c0 + cc] = fmaxf(a + mx, 0.0f);
    }
}

// ------------------------- head: pool + MLP -----------------------
__global__ __launch_bounds__(256) void finalk(const float* __restrict__ H3,
                                              const float* __restrict__ Wf1,
                                              const float* __restrict__ bf1,
                                              const float* __restrict__ gf,
                                              const float* __restrict__ bef,
                                              const float* __restrict__ Wf2,
                                              const float* __restrict__ bf2,
                                              float* __restrict__ out) {
    __shared__ float p[256];
    __shared__ float f1[128];
    int b = blockIdx.x, t = threadIdx.x;
    const float* Hb = H3 + (size_t)b * 256 * 256;
    float m = -FLTMAX;
    for (int i = 0; i < 256; i++) m = fmaxf(m, Hb[(size_t)i * 256 + t]);
    p[t] = m;
    __syncthreads();
    if (t < 128) {
        float acc = bf1[t];
        for (int k = 0; k < 256; k++) acc += p[k] * Wf1[k * 128 + t];
        f1[t] = fmaxf(gf[t] * (acc * BN_SCALE) + bef[t], 0.0f);
    }
    __syncthreads();
    if (t < 12) {
        float acc = bf2[t];
        for (int k = 0; k < 128; k++) acc += f1[k] * Wf2[k * 12 + t];
        out[b * 12 + t] = acc;
    }
}

// ------------------------- launch ---------------------------------
static const int KNNF_SMEM = (256 + 2176 + 4224 + 16640) * 4;  // 93,184 bytes

extern "C" void kernel_launch(void* const* d_in, const int* in_sizes, int n_in,
                              void* d_out, int out_size) {
    const float* x   = (const float*)d_in[0];
    const float* W1  = (const float*)d_in[1];
    const float* b1  = (const float*)d_in[2];
    const float* g1  = (const float*)d_in[3];
    const float* be1 = (const float*)d_in[4];
    const float* W2  = (const float*)d_in[5];
    const float* b2  = (const float*)d_in[6];
    const float* g2  = (const float*)d_in[7];
    const float* be2 = (const float*)d_in[8];
    const float* W3  = (const float*)d_in[9];
    const float* b3  = (const float*)d_in[10];
    const float* g3  = (const float*)d_in[11];
    const float* be3 = (const float*)d_in[12];
    const float* Wf1 = (const float*)d_in[13];
    const float* bf1 = (const float*)d_in[14];
    const float* gf  = (const float*)d_in[15];
    const float* bef = (const float*)d_in[16];
    const float* Wf2 = (const float*)d_in[17];
    const float* bf2 = (const float*)d_in[18];
    float* out = (float*)d_out;

    cudaFuncSetAttribute(knnf<64>,  cudaFuncAttributeMaxDynamicSharedMemorySize, KNNF_SMEM);
    cudaFuncSetAttribute(knnf<128>, cudaFuncAttributeMaxDynamicSharedMemorySize, KNNF_SMEM);

    void *pT, *ph1, *ph2, *ph3, *pidx;
    void *pW1p, *pb1p, *pW2p, *pb2p, *pW3p, *pb3p;
    cudaGetSymbolAddress(&pT,  g_T);
    cudaGetSymbolAddress(&ph1, g_h1);
    cudaGetSymbolAddress(&ph2, g_h2);
    cudaGetSymbolAddress(&ph3, g_h3);
    cudaGetSymbolAddress(&pidx, g_idx);
    cudaGetSymbolAddress(&pW1p, g_W1p); cudaGetSymbolAddress(&pb1p, g_b1p);
    cudaGetSymbolAddress(&pW2p, g_W2p); cudaGetSymbolAddress(&pb2p, g_b2p);
    cudaGetSymbolAddress(&pW3p, g_W3p); cudaGetSymbolAddress(&pb3p, g_b3p);
    float* T   = (float*)pT;
    float* h1  = (float*)ph1;
    float* h2  = (float*)ph2;
    float* h3  = (float*)ph3;
    int*   idx = (int*)pidx;

    prepw<<<8,   256>>>(W1, b1, g1, be1, (float*)pW1p, (float*)pb1p, 6,   64);
    prepw<<<64,  256>>>(W2, b2, g2, be2, (float*)pW2p, (float*)pb2p, 64,  128);
    prepw<<<256, 256>>>(W3, b3, g3, be3, (float*)pW3p, (float*)pb3p, 128, 256);

    // ---- layer 1 (D=6 -> C=64)
    knn6<<<128, 512>>>(x, idx);
    sgemm6<<<4096, 256>>>(x, (float*)pW1p, (float*)pb1p, T);
    edgemax<<<dim3(128, 2), 256>>>(T, idx, h1, 64);

    // ---- layer 2 (D=64 -> C=128)
    knnf<64><<<dim3(4, 128), 256, KNNF_SMEM>>>(h1, idx);
    sgemm<<<dim3(2, 256), 256>>>(h1, (float*)pW2p, (float*)pb2p, T, 32768, 64, 256);
    edgemax<<<dim3(128, 4), 256>>>(T, idx, h2, 128);

    // ---- layer 3 (D=128 -> C=256)
    knnf<128><<<dim3(4, 128), 256, KNNF_SMEM>>>(h2, idx);
    sgemm<<<dim3(4, 256), 256>>>(h2, (float*)pW3p, (float*)pb3p, T, 32768, 128, 512);
    edgemax<<<dim3(128, 8), 256>>>(T, idx, h3, 256);

    // ---- head
    finalk<<<128, 256>>>(h3, Wf1, bf1, gf, bef, Wf2, bf2, out);
}

// round 5
// speedup vs baseline: 1.5907x; 1.3576x over previous
#include <cuda_runtime.h>
#include <cstdint>

#define BN_SCALE 0.9999950000374997f
#define FLTMAX 3.402823466e+38f

typedef unsigned long long u64;

// packed fp32x2 helpers — bit-exact IEEE fp32 per lane
__device__ __forceinline__ void fma2(u64& d, u64 a, u64 b) {
    asm("fma.rn.f32x2 %0,%1,%2,%0;" : "+l"(d) : "l"(a), "l"(b));
}
__device__ __forceinline__ float2 unpk(u64 v) {
    float2 r; asm("mov.b64 {%0,%1},%2;" : "=f"(r.x), "=f"(r.y) : "l"(v)); return r;
}
__device__ __forceinline__ u64 pk2(float v) {
    u64 r; asm("mov.b64 %0,{%1,%1};" : "=l"(r) : "f"(v)); return r;
}

// ---- (d, j) packed key: exact lexicographic (d asc, j asc) ----
__device__ __forceinline__ u64 packdj(float d, int j) {
    unsigned u = __float_as_uint(d);
    u = ((int)u < 0) ? ~u : (u | 0x80000000u);
    return ((u64)u << 32) | (unsigned)j;
}
__device__ __forceinline__ void ce(u64& a, u64& b) {
    if (b < a) { u64 t = a; a = b; b = t; }
}
__device__ __forceinline__ void sort8(u64 k[8]) {
    ce(k[0],k[1]); ce(k[2],k[3]); ce(k[4],k[5]); ce(k[6],k[7]);
    ce(k[0],k[2]); ce(k[1],k[3]); ce(k[4],k[6]); ce(k[5],k[7]);
    ce(k[1],k[2]); ce(k[5],k[6]);
    ce(k[0],k[4]); ce(k[1],k[5]); ce(k[2],k[6]); ce(k[3],k[7]);
    ce(k[2],k[4]); ce(k[3],k[5]);
    ce(k[1],k[2]); ce(k[3],k[4]); ce(k[5],k[6]);
}
// warp-cooperative top-16 of 256 candidates; lane holds 8 sorted keys,
// candidate j resides in lane (j & 31). Returns t-th winner's j in lane t.
__device__ __forceinline__ int top16_warp(u64 k[8], int lane) {
    int myj = 0;
    #pragma unroll
    for (int t = 0; t < 16; ++t) {
        u64 w = k[0];
        #pragma unroll
        for (int o = 16; o; o >>= 1) {
            u64 v = __shfl_xor_sync(0xFFFFFFFFu, w, o);
            if (v < w) w = v;
        }
        int wj = (int)(unsigned)(w & 0xFFFFFFFFull);
        if (lane == t) myj = wj;
        if (lane == (wj & 31)) {
            k[0]=k[1]; k[1]=k[2]; k[2]=k[3]; k[3]=k[4];
            k[4]=k[5]; k[5]=k[6]; k[6]=k[7];
            k[7]=0xFFFFFFFFFFFFFFFFull;
        }
    }
    return myj;
}

// ------------------------- device scratch -------------------------
__device__ float g_T[32768 * 512];
__device__ float g_h1[32768 * 64];
__device__ float g_h2[32768 * 128];
__device__ float g_h3[32768 * 256];
__device__ int   g_idx[128 * 256 * 16];
__device__ float g_W1p[6 * 128];   __device__ float g_b1p[128];
__device__ float g_W2p[64 * 256];  __device__ float g_b2p[256];
__device__ float g_W3p[128 * 512]; __device__ float g_b3p[512];

// ------------------------- weight prep ----------------------------
__global__ void prepw(const float* __restrict__ W, const float* __restrict__ b,
                      const float* __restrict__ g, const float* __restrict__ be,
                      float* __restrict__ Wp, float* __restrict__ bp,
                      int Cin, int C) {
    int n2 = 2 * C;
    int total = Cin * n2;
    for (int t = blockIdx.x * blockDim.x + threadIdx.x; t < total + n2;
         t += gridDim.x * blockDim.x) {
        if (t < total) {
            int k = t / n2, c = t % n2;
            float out;
            if (c < C) out = g[c] * BN_SCALE * (W[k * C + c] - W[(Cin + k) * C + c]);
            else { int cc = c - C; out = g[cc] * BN_SCALE * W[(Cin + k) * C + cc]; }
            Wp[t] = out;
        } else {
            int c = t - total;
            bp[c] = (c < C) ? (g[c] * BN_SCALE * b[c] + be[c]) : 0.0f;
        }
    }
}

// ------------------------- fused KNN, D=6 (layer 1) ---------------
// warp per row; lane handles candidates j = u*32+lane (u=0..7).
__global__ __launch_bounds__(512) void knn6(const float* __restrict__ X,
                                            int* __restrict__ idx) {
    __shared__ float pts[6][256];
    __shared__ float sqs[256];
    int b = blockIdx.x, tid = threadIdx.x;
    if (tid < 256) {
        const float* xp = X + ((size_t)b * 256 + tid) * 6;
        float s = 0.0f;
        #pragma unroll
        for (int k = 0; k < 6; k++) { float v = xp[k]; pts[k][tid] = v; s += v * v; }
        sqs[tid] = s;
    }
    __syncthreads();
    int warp = tid >> 5, lane = tid & 31;
    for (int rr = 0; rr < 16; ++rr) {
        int i = warp * 16 + rr;
        float x0 = pts[0][i], x1 = pts[1][i], x2 = pts[2][i];
        float x3 = pts[3][i], x4 = pts[4][i], x5 = pts[5][i];
        float sqi = sqs[i];
        u64 k[8];
        #pragma unroll
        for (int u = 0; u < 8; ++u) {
            int j = u * 32 + lane;
            float dot = x0 * pts[0][j] + x1 * pts[1][j] + x2 * pts[2][j]
                      + x3 * pts[3][j] + x4 * pts[4][j] + x5 * pts[5][j];
            float d = sqi + sqs[j] - 2.0f * dot;
            if (j == i) d = FLTMAX;
            k[u] = packdj(d, j);
        }
        sort8(k);
        int myj = top16_warp(k, lane);
        if (lane < 16) idx[((size_t)b * 256 + i) * 16 + lane] = myj;
    }
}

// ------------------------- fused KNN, D in {64,128} ---------------
template<int D>
__global__ __launch_bounds__(256) void knnf(const float* __restrict__ H,
                                            int* __restrict__ idx) {
    extern __shared__ float sm[];
    float* sqs = sm;                 // 256
    float* As  = sm + 256;           // 2*16*68  = 2176
    float* Bs  = sm + 256 + 2176;    // 2*16*132 = 4224
    float* ds  = sm + 256 + 2176 + 4224; // 64*260 = 16640
    int b = blockIdx.y;
    int i0 = blockIdx.x * 64;
    const float* Hb = H + (size_t)b * 256 * D;
    int tid = threadIdx.x;
    int ty = tid >> 5, tx = tid & 31;

    {
        const float4* rp = (const float4*)(Hb + (size_t)tid * D);
        float s = 0.0f;
        #pragma unroll
        for (int u = 0; u < D / 4; ++u) {
            float4 v = rp[u];
            s += v.x * v.x + v.y * v.y + v.z * v.z + v.w * v.w;
        }
        sqs[tid] = s;
    }

    int ar = tid & 63,  ak4 = (tid >> 6) * 4;
    int br = tid & 127, bk8 = (tid >> 7) * 8;

    for (int h = 0; h < 2; ++h) {
        int j0 = h * 128;
        u64 acc2[4][4];
        #pragma unroll
        for (int p = 0; p < 4; p++)
            #pragma unroll
            for (int s = 0; s < 4; s++) acc2[p][s] = 0ull;

        float4 pa  = *(const float4*)(Hb + (size_t)(i0 + ar) * D + ak4);
        float4 pb0 = *(const float4*)(Hb + (size_t)(j0 + br) * D + bk8);
        float4 pb1 = *(const float4*)(Hb + (size_t)(j0 + br) * D + bk8 + 4);
        int buf = 0;

        for (int k0 = 0; k0 < D; k0 += 16) {
            float* Ab = As + buf * 1088;
            float* Bb = Bs + buf * 2112;
            Ab[(ak4 + 0) * 68 + ar] = pa.x;
            Ab[(ak4 + 1) * 68 + ar] = pa.y;
            Ab[(ak4 + 2) * 68 + ar] = pa.z;
            Ab[(ak4 + 3) * 68 + ar] = pa.w;
            Bb[(bk8 + 0) * 132 + br] = pb0.x;
            Bb[(bk8 + 1) * 132 + br] = pb0.y;
            Bb[(bk8 + 2) * 132 + br] = pb0.z;
            Bb[(bk8 + 3) * 132 + br] = pb0.w;
            Bb[(bk8 + 4) * 132 + br] = pb1.x;
            Bb[(bk8 + 5) * 132 + br] = pb1.y;
            Bb[(bk8 + 6) * 132 + br] = pb1.z;
            Bb[(bk8 + 7) * 132 + br] = pb1.w;
            __syncthreads();
            if (k0 + 16 < D) {
                pa  = *(const float4*)(Hb + (size_t)(i0 + ar) * D + k0 + 16 + ak4);
                pb0 = *(const float4*)(Hb + (size_t)(j0 + br) * D + k0 + 16 + bk8);
                pb1 = *(const float4*)(Hb + (size_t)(j0 + br) * D + k0 + 16 + bk8 + 4);
            }
            #pragma unroll
            for (int kk = 0; kk < 16; ++kk) {
                float4 a0 = *(const float4*)&Ab[kk * 68 + ty * 8];
                float4 a1 = *(const float4*)&Ab[kk * 68 + ty * 8 + 4];
                u64 ap[4];
                ap[0] = ((const u64*)&a0)[0]; ap[1] = ((const u64*)&a0)[1];
                ap[2] = ((const u64*)&a1)[0]; ap[3] = ((const u64*)&a1)[1];
                float4 bv = *(const float4*)&Bb[kk * 132 + tx * 4];
                u64 bd0 = pk2(bv.x), bd1 = pk2(bv.y), bd2 = pk2(bv.z), bd3 = pk2(bv.w);
                #pragma unroll
                for (int p = 0; p < 4; p++) {
                    fma2(acc2[p][0], ap[p], bd0);
                    fma2(acc2[p][1], ap[p], bd1);
                    fma2(acc2[p][2], ap[p], bd2);
                    fma2(acc2[p][3], ap[p], bd3);
                }
            }
            buf ^= 1;
        }

        #pragma unroll
        for (int p = 0; p < 4; p++) {
            float2 c0 = unpk(acc2[p][0]);
            float2 c1 = unpk(acc2[p][1]);
            float2 c2 = unpk(acc2[p][2]);
            float2 c3 = unpk(acc2[p][3]);
            int col = j0 + tx * 4;
            #pragma unroll
            for (int e = 0; e < 2; e++) {
                int row = ty * 8 + 2 * p + e;
                float si = sqs[i0 + row];
                float d0 = (e == 0) ? c0.x : c0.y;
                float d1 = (e == 0) ? c1.x : c1.y;
                float d2_ = (e == 0) ? c2.x : c2.y;
                float d3 = (e == 0) ? c3.x : c3.y;
                float4 v;
                v.x = si + sqs[col + 0] - 2.0f * d0;
                v.y = si + sqs[col + 1] - 2.0f * d1;
                v.z = si + sqs[col + 2] - 2.0f * d2_;
                v.w = si + sqs[col + 3] - 2.0f * d3;
                int gi = i0 + row;
                if (gi == col + 0) v.x = FLTMAX;
                if (gi == col + 1) v.y = FLTMAX;
                if (gi == col + 2) v.z = FLTMAX;
                if (gi == col + 3) v.w = FLTMAX;
                *(float4*)&ds[row * 260 + col] = v;
            }
        }
    }
    __syncthreads();

    // warp-parallel top-16: warp w handles rows w*8 .. w*8+7
    {
        int warp = tid >> 5, lane = tid & 31;
        for (int rr = 0; rr < 8; ++rr) {
            int row = warp * 8 + rr;
            const float* dr = &ds[row * 260];
            u64 k[8];
            #pragma unroll
            for (int u = 0; u < 8; ++u) {
                int j = u * 32 + lane;
                k[u] = packdj(dr[j], j);
            }
            sort8(k);
            int myj = top16_warp(k, lane);
            if (lane < 16) idx[((size_t)b * 256 + i0 + row) * 16 + lane] = myj;
        }
    }
}

// ------------------------- layer-1 SGEMM (K=6, N=128) -------------
__global__ __launch_bounds__(256) void sgemm6(const float* __restrict__ X,
                                              const float* __restrict__ Wp,
                                              const float* __restrict__ bp,
                                              float* __restrict__ T) {
    __shared__ float Ws[6][128];
    __shared__ float bs[128];
    int tid = threadIdx.x;
    if (tid < 128) bs[tid] = bp[tid];
    for (int t = tid; t < 768; t += 256) Ws[t / 128][t % 128] = Wp[t];
    __syncthreads();
    int warp = tid >> 5, lane = tid & 31;
    int row = blockIdx.x * 8 + warp;
    const float* xr = X + (size_t)row * 6;
    float x0 = xr[0], x1 = xr[1], x2 = xr[2], x3 = xr[3], x4 = xr[4], x5 = xr[5];
    int c = lane * 4;
    float4 o;
    #pragma unroll
    for (int u = 0; u < 4; ++u) {
        float v = bs[c + u];
        v += x0 * Ws[0][c + u]; v += x1 * Ws[1][c + u]; v += x2 * Ws[2][c + u];
        v += x3 * Ws[3][c + u]; v += x4 * Ws[4][c + u]; v += x5 * Ws[5][c + u];
        ((float*)&o)[u] = v;
    }
    *(float4*)&T[(size_t)row * 128 + c] = o;
}

// ------------------------- main SGEMM -----------------------------
// 128 threads, 128x128 block tile, 16 rows x 8 cols per thread, FFMA2
// with pre-duplicated B in smem (1 B/MAC at the doubled FFMA2 rate).
// Thread (tx,ty): rows ty*16..+15, cols {2tx+32s, 2tx+1+32s : s=0..3}.
// K must be a multiple of 16 (K in {64,128}).
__global__ __launch_bounds__(128) void sgemm(const float* __restrict__ A,
                                             const float* __restrict__ W,
                                             const float* __restrict__ bias,
                                             float* __restrict__ C,
                                             int K, int N) {
    extern __shared__ float smx[];
    float* Asm = smx;            // [2][16][132]
    float* Bsm = smx + 4224;     // [2][16][264] duplicated
    int i0 = blockIdx.y * 128, j0 = blockIdx.x * 128;
    int tid = threadIdx.x;
    int tx = tid & 15, ty = tid >> 4;
    int bk = tid & 15, bg = (tid >> 4) * 16;   // B stage: k-row bk, cols bg..bg+15

    u64 acc[8][8];
    #pragma unroll
    for (int p = 0; p < 8; p++)
        #pragma unroll
        for (int s = 0; s < 8; s++) acc[p][s] = 0ull;

    const float* Arow = A + (size_t)(i0 + tid) * K;
    float4 ga[4], gb[4];
    #pragma unroll
    for (int u = 0; u < 4; ++u) ga[u] = *(const float4*)&Arow[u * 4];
    #pragma unroll
    for (int u = 0; u < 4; ++u) gb[u] = *(const float4*)&W[(size_t)bk * N + j0 + bg + u * 4];
    // store stage 0
    {
        float* Aw = Asm; float* Bw = Bsm;
        #pragma unroll
        for (int u = 0; u < 4; ++u) {
            Aw[(u * 4 + 0) * 132 + tid] = ga[u].x;
            Aw[(u * 4 + 1) * 132 + tid] = ga[u].y;
            Aw[(u * 4 + 2) * 132 + tid] = ga[u].z;
            Aw[(u * 4 + 3) * 132 + tid] = ga[u].w;
            float4 v = gb[u];
            *(float4*)&Bw[bk * 264 + 2 * (bg + u * 4)]     = make_float4(v.x, v.x, v.y, v.y);
            *(float4*)&Bw[bk * 264 + 2 * (bg + u * 4) + 4] = make_float4(v.z, v.z, v.w, v.w);
        }
    }
    __syncthreads();

    int nsteps = K >> 4;
    for (int st = 0; st < nsteps; ++st) {
        int buf = st & 1;
        bool more = (st + 1 < nsteps);
        if (more) {
            int k0 = (st + 1) << 4;
            #pragma unroll
            for (int u = 0; u < 4; ++u) ga[u] = *(const float4*)&Arow[k0 + u * 4];
            #pragma unroll
            for (int u = 0; u < 4; ++u) gb[u] = *(const float4*)&W[(size_t)(k0 + bk) * N + j0 + bg + u * 4];
        }
        const float* Ab = Asm + buf * 2112;
        const float* Bb = Bsm + buf * 4224;
        #pragma unroll
        for (int kk = 0; kk < 16; ++kk) {
            const float4* arp = (const float4*)&Ab[kk * 132 + ty * 16];
            float4 a0 = arp[0], a1 = arp[1], a2 = arp[2], a3 = arp[3];
            u64 ap[8];
            ap[0] = ((const u64*)&a0)[0]; ap[1] = ((const u64*)&a0)[1];
            ap[2] = ((const u64*)&a1)[0]; ap[3] = ((const u64*)&a1)[1];
            ap[4] = ((const u64*)&a2)[0]; ap[5] = ((const u64*)&a2)[1];
            ap[6] = ((const u64*)&a3)[0]; ap[7] = ((const u64*)&a3)[1];
            u64 bp[8];
            #pragma unroll
            for (int s = 0; s < 4; ++s) {
                float4 bv = *(const float4*)&Bb[kk * 264 + 4 * tx + 64 * s];
                bp[2 * s]     = ((const u64*)&bv)[0];
                bp[2 * s + 1] = ((const u64*)&bv)[1];
            }
            #pragma unroll
            for (int p = 0; p < 8; p++)
                #pragma unroll
                for (int s = 0; s < 8; s++)
                    fma2(acc[p][s], ap[p], bp[s]);
        }
        if (more) {
            int nb = buf ^ 1;
            float* Aw = Asm + nb * 2112;
            float* Bw = Bsm + nb * 4224;
            #pragma unroll
            for (int u = 0; u < 4; ++u) {
                Aw[(u * 4 + 0) * 132 + tid] = ga[u].x;
                Aw[(u * 4 + 1) * 132 + tid] = ga[u].y;
                Aw[(u * 4 + 2) * 132 + tid] = ga[u].z;
                Aw[(u * 4 + 3) * 132 + tid] = ga[u].w;
                float4 v = gb[u];
                *(float4*)&Bw[bk * 264 + 2 * (bg + u * 4)]     = make_float4(v.x, v.x, v.y, v.y);
                *(float4*)&Bw[bk * 264 + 2 * (bg + u * 4) + 4] = make_float4(v.z, v.z, v.w, v.w);
            }
            __syncthreads();
        }
    }

    // epilogue: rows ty*16+2p+e, col pairs (2tx+32s, 2tx+1+32s)
    #pragma unroll
    for (int p = 0; p < 8; p++) {
        float2 c[8];
        #pragma unroll
        for (int s = 0; s < 8; s++) c[s] = unpk(acc[p][s]);
        #pragma unroll
        for (int e = 0; e < 2; e++) {
            int row = i0 + ty * 16 + 2 * p + e;
            #pragma unroll
            for (int s4 = 0; s4 < 4; s4++) {
                int col = j0 + 2 * tx + 32 * s4;
                float2 v;
                v.x = ((e == 0) ? c[2 * s4].x     : c[2 * s4].y)     + bias[col];
                v.y = ((e == 0) ? c[2 * s4 + 1].x : c[2 * s4 + 1].y) + bias[col + 1];
                *(float2*)&C[(size_t)row * N + col] = v;
            }
        }
    }
}

// ------------------------- edge max -------------------------------
__global__ __launch_bounds__(256) void edgemax(const float* __restrict__ T,
                                               const int* __restrict__ idx,
                                               float* __restrict__ H, int C) {
    __shared__ float sc[256][32];
    int b = blockIdx.x;
    int c0 = blockIdx.y * 32;
    int cc = threadIdx.x & 31;
    int i0 = threadIdx.x >> 5;
    const float* Tb = T + (size_t)b * 256 * 2 * C;

    for (int j = i0; j < 256; j += 8)
        sc[j][cc] = Tb[(size_t)j * 2 * C + C + c0 + cc];
    __syncthreads();

    for (int i = i0; i < 256; i += 8) {
        const int* ip = idx + ((size_t)b * 256 + i) * 16;
        float mx = -FLTMAX;
        #pragma unroll
        for (int k = 0; k < 16; ++k) {
            int j = ip[k];
            mx = fmaxf(mx, sc[j][cc]);
        }
        float a = Tb[(size_t)i * 2 * C + c0 + cc];
        H[((size_t)b * 256 + i) * C + c0 + cc] = fmaxf(a + mx, 0.0f);
    }
}

// ------------------------- head: pool + MLP -----------------------
__global__ __launch_bounds__(256) void finalk(const float* __restrict__ H3,
                                              const float* __restrict__ Wf1,
                                              const float* __restrict__ bf1,
                                              const float* __restrict__ gf,
                                              const float* __restrict__ bef,
                                              const float* __restrict__ Wf2,
                                              const float* __restrict__ bf2,
                                              float* __restrict__ out) {
    __shared__ float p[256];
    __shared__ float f1[128];
    int b = blockIdx.x, t = threadIdx.x;
    const float* Hb = H3 + (size_t)b * 256 * 256;
    float m = -FLTMAX;
    for (int i = 0; i < 256; i++) m = fmaxf(m, Hb[(size_t)i * 256 + t]);
    p[t] = m;
    __syncthreads();
    if (t < 128) {
        float acc = bf1[t];
        for (int k = 0; k < 256; k++) acc += p[k] * Wf1[k * 128 + t];
        f1[t] = fmaxf(gf[t] * (acc * BN_SCALE) + bef[t], 0.0f);
    }
    __syncthreads();
    if (t < 12) {
        float acc = bf2[t];
        for (int k = 0; k < 128; k++) acc += f1[k] * Wf2[k * 12 + t];
        out[b * 12 + t] = acc;
    }
}

// ------------------------- launch ---------------------------------
static const int KNNF_SMEM  = (256 + 2176 + 4224 + 16640) * 4;  // 93,184 B
static const int SGEMM_SMEM = (4224 + 8448) * 4;                // 50,688 B

extern "C" void kernel_launch(void* const* d_in, const int* in_sizes, int n_in,
                              void* d_out, int out_size) {
    const float* x   = (const float*)d_in[0];
    const float* W1  = (const float*)d_in[1];
    const float* b1  = (const float*)d_in[2];
    const float* g1  = (const float*)d_in[3];
    const float* be1 = (const float*)d_in[4];
    const float* W2  = (const float*)d_in[5];
    const float* b2  = (const float*)d_in[6];
    const float* g2  = (const float*)d_in[7];
    const float* be2 = (const float*)d_in[8];
    const float* W3  = (const float*)d_in[9];
    const float* b3  = (const float*)d_in[10];
    const float* g3  = (const float*)d_in[11];
    const float* be3 = (const float*)d_in[12];
    const float* Wf1 = (const float*)d_in[13];
    const float* bf1 = (const float*)d_in[14];
    const float* gf  = (const float*)d_in[15];
    const float* bef = (const float*)d_in[16];
    const float* Wf2 = (const float*)d_in[17];
    const float* bf2 = (const float*)d_in[18];
    float* out = (float*)d_out;

    cudaFuncSetAttribute(knnf<64>,  cudaFuncAttributeMaxDynamicSharedMemorySize, KNNF_SMEM);
    cudaFuncSetAttribute(knnf<128>, cudaFuncAttributeMaxDynamicSharedMemorySize, KNNF_SMEM);
    cudaFuncSetAttribute(sgemm,     cudaFuncAttributeMaxDynamicSharedMemorySize, SGEMM_SMEM);

    void *pT, *ph1, *ph2, *ph3, *pidx;
    void *pW1p, *pb1p, *pW2p, *pb2p, *pW3p, *pb3p;
    cudaGetSymbolAddress(&pT,  g_T);
    cudaGetSymbolAddress(&ph1, g_h1);
    cudaGetSymbolAddress(&ph2, g_h2);
    cudaGetSymbolAddress(&ph3, g_h3);
    cudaGetSymbolAddress(&pidx, g_idx);
    cudaGetSymbolAddress(&pW1p, g_W1p); cudaGetSymbolAddress(&pb1p, g_b1p);
    cudaGetSymbolAddress(&pW2p, g_W2p); cudaGetSymbolAddress(&pb2p, g_b2p);
    cudaGetSymbolAddress(&pW3p, g_W3p); cudaGetSymbolAddress(&pb3p, g_b3p);
    float* T   = (float*)pT;
    float* h1  = (float*)ph1;
    float* h2  = (float*)ph2;
    float* h3  = (float*)ph3;
    int*   idx = (int*)pidx;

    prepw<<<8,   256>>>(W1, b1, g1, be1, (float*)pW1p, (float*)pb1p, 6,   64);
    prepw<<<64,  256>>>(W2, b2, g2, be2, (float*)pW2p, (float*)pb2p, 64,  128);
    prepw<<<256, 256>>>(W3, b3, g3, be3, (float*)pW3p, (float*)pb3p, 128, 256);

    // ---- layer 1 (D=6 -> C=64)
    knn6<<<128, 512>>>(x, idx);
    sgemm6<<<4096, 256>>>(x, (float*)pW1p, (float*)pb1p, T);
    edgemax<<<dim3(128, 2), 256>>>(T, idx, h1, 64);

    // ---- layer 2 (D=64 -> C=128)
    knnf<64><<<dim3(4, 128), 256, KNNF_SMEM>>>(h1, idx);
    sgemm<<<dim3(2, 256), 128, SGEMM_SMEM>>>(h1, (float*)pW2p, (float*)pb2p, T, 64, 256);
    edgemax<<<dim3(128, 4), 256>>>(T, idx, h2, 128);

    // ---- layer 3 (D=128 -> C=256)
    knnf<128><<<dim3(4, 128), 256, KNNF_SMEM>>>(h2, idx);
    sgemm<<<dim3(4, 256), 128, SGEMM_SMEM>>>(h2, (float*)pW3p, (float*)pb3p, T, 128, 512);
    edgemax<<<dim3(128, 8), 256>>>(T, idx, h3, 256);

    // ---- head
    finalk<<<128, 256>>>(h3, Wf1, bf1, gf, bef, Wf2, bf2, out);
}